// round 15
// baseline (speedup 1.0000x reference)
#include <cuda_runtime.h>
#include <cuda_fp16.h>
#include <math.h>
#include <stdint.h>

// Problem constants
constexpr int NB = 2;
constexpr int NS = 2048;
constexpr int ND = 1024;
constexpr int NH = 16;
constexpr int DH = 64;

// Chunked scheduling over (q-tile, 64-key-tile) units  [R10 winner]
constexpr int NQT   = NB * NH * (NS / 128);   // 512 q-tiles
constexpr int NT    = NS / 64;                // 32 key tiles per q-tile
constexpr int UNITS = NQT * NT;               // 16384
constexpr int GRID_ATTN = 444;                // 3 CTAs/SM x 148 SMs = one wave
constexpr int CHUNK = (UNITS + GRID_ATTN - 1) / GRID_ATTN;  // 37 (>=32 -> <=2 slices/tile)

// log2(e) folded into Q pre-scale: softmax exp(s) == ex2(s * log2e)
constexpr float QSCALE = 0.125f * 1.4426950408889634f;

// Scratch: projected Q/K/V in fp16, [b,h,s,e]
__device__ __half g_Q[(size_t)NB * NH * NS * DH];
__device__ __half g_K[(size_t)NB * NH * NS * DH];
__device__ __half g_V[(size_t)NB * NH * NS * DH];
// Partial (unnormalized) attention outputs: [slice][qt][row][col] + row sums
__device__ float g_pO[2][NQT][128 * 64];
__device__ float g_pL[2][NQT][128];
// Per-q-tile arrival flags for fused combining (zero-init; combiner resets)
__device__ int g_flag[NQT];

__device__ __forceinline__ uint32_t smem_u32(const void* p) {
    uint32_t a;
    asm("{ .reg .u64 t; cvta.to.shared.u64 t, %1; cvt.u32.u64 %0, t; }"
        : "=r"(a) : "l"(p));
    return a;
}
__device__ __forceinline__ void mma_f16(float c[4], const uint32_t a[4],
                                        uint32_t b0, uint32_t b1) {
    asm volatile(
        "mma.sync.aligned.m16n8k16.row.col.f32.f16.f16.f32 "
        "{%0,%1,%2,%3}, {%4,%5,%6,%7}, {%8,%9}, {%0,%1,%2,%3};"
        : "+f"(c[0]), "+f"(c[1]), "+f"(c[2]), "+f"(c[3])
        : "r"(a[0]), "r"(a[1]), "r"(a[2]), "r"(a[3]), "r"(b0), "r"(b1));
}
#define LDSM_X4(r0, r1, r2, r3, addr) \
    asm volatile("ldmatrix.sync.aligned.m8n8.x4.shared.b16 {%0,%1,%2,%3}, [%4];" \
                 : "=r"(r0), "=r"(r1), "=r"(r2), "=r"(r3) : "r"(addr))
#define LDSM_X4_T(r0, r1, r2, r3, addr) \
    asm volatile("ldmatrix.sync.aligned.m8n8.x4.trans.shared.b16 {%0,%1,%2,%3}, [%4];" \
                 : "=r"(r0), "=r"(r1), "=r"(r2), "=r"(r3) : "r"(addr))
#define CP_ASYNC16(dst, src) \
    asm volatile("cp.async.cg.shared.global [%0], [%1], 16;" :: "r"(dst), "l"(src))
#define CP_COMMIT() asm volatile("cp.async.commit_group;")
#define CP_WAIT0()  asm volatile("cp.async.wait_group 0;")

__device__ __forceinline__ uint32_t ex2_f16x2(uint32_t x) {
    uint32_t r;
    asm("ex2.approx.f16x2 %0, %1;" : "=r"(r) : "r"(x));
    return r;
}
__device__ __forceinline__ uint32_t pack_h2(float a, float b) {
    __half2 h = __floats2half2_rn(a, b);
    return *(uint32_t*)&h;
}
__device__ __forceinline__ __half2 as_h2(uint32_t x) { return *(__half2*)&x; }

constexpr int HSTR = 72;  // halves per smem row (144B): conflict-free ldmatrix

// ---------------------------------------------------------------------------
// Kernel 1: per-head QKV projection on fp16 mma (R10's serial 128-row
// version — best measured at 17.9us). CTA = 128 threads.
// ---------------------------------------------------------------------------
__global__ __launch_bounds__(128) void proj_kernel(
    const float* __restrict__ seqs,
    const float* __restrict__ Wq, const float* __restrict__ bq,
    const float* __restrict__ Wk, const float* __restrict__ bk,
    const float* __restrict__ Wv, const float* __restrict__ bv)
{
    __shared__ __half xs[128 * HSTR];
    __shared__ __half ws[64 * HSTR];

    const int tid  = threadIdx.x;
    const int lane = tid & 31;
    const int w    = tid >> 5;
    const int g    = lane >> 2;
    const int t    = lane & 3;
    const int r0   = w * 32;

    const int h   = blockIdx.y;
    const int gr0 = blockIdx.x * 128;
    const int b   = gr0 / NS;
    const int s0  = gr0 - b * NS;
    const int bh  = b * NH + h;

    #pragma unroll
    for (int it = 0; it < 16; it++) {
        int i = it * 128 + tid;
        int r = i >> 4, c4 = i & 15;
        float4 f = *(const float4*)&seqs[(size_t)(gr0 + r) * ND + h * 64 + c4 * 4];
        *(uint32_t*)&xs[r * HSTR + c4 * 4]     = pack_h2(f.x, f.y);
        *(uint32_t*)&xs[r * HSTR + c4 * 4 + 2] = pack_h2(f.z, f.w);
    }
    __syncthreads();

    const uint32_t xb = smem_u32(xs);
    const uint32_t wb = smem_u32(ws);
    const uint32_t a_lofs =
        (uint32_t)(((r0 + (lane & 15)) * HSTR + 8 * (lane >> 4)) * 2);
    const uint32_t b_lofs =
        (uint32_t)(((8 * (lane >> 4) + (lane & 7)) * HSTR + 8 * ((lane >> 3) & 1)) * 2);

    uint32_t ax[2][4][4];
    #pragma unroll
    for (int mb = 0; mb < 2; mb++)
        #pragma unroll
        for (int kk = 0; kk < 4; kk++)
            LDSM_X4(ax[mb][kk][0], ax[mb][kk][1], ax[mb][kk][2], ax[mb][kk][3],
                    xb + a_lofs + (uint32_t)(mb * 16 * HSTR * 2 + kk * 32));

    #pragma unroll
    for (int m = 0; m < 3; m++) {
        const float* W    = (m == 0) ? Wq : ((m == 1) ? Wk : Wv);
        const float* bias = (m == 0) ? bq : ((m == 1) ? bk : bv);
        __half* dst       = (m == 0) ? g_Q : ((m == 1) ? g_K : g_V);
        const float sc    = (m == 0) ? QSCALE : 1.0f;

        __syncthreads();
        #pragma unroll
        for (int it = 0; it < 8; it++) {
            int i = it * 128 + tid;
            int r = i >> 4, c4 = i & 15;
            float4 f = *(const float4*)&W[h * 4096 + r * 64 + c4 * 4];
            *(uint32_t*)&ws[r * HSTR + c4 * 4]     = pack_h2(f.x, f.y);
            *(uint32_t*)&ws[r * HSTR + c4 * 4 + 2] = pack_h2(f.z, f.w);
        }
        __syncthreads();

        float cC[2][8][4];
        #pragma unroll
        for (int mb = 0; mb < 2; mb++)
            #pragma unroll
            for (int nb = 0; nb < 8; nb++)
                #pragma unroll
                for (int r = 0; r < 4; r++) cC[mb][nb][r] = 0.0f;

        #pragma unroll
        for (int kk = 0; kk < 4; kk++) {
            #pragma unroll
            for (int nb2 = 0; nb2 < 4; nb2++) {
                uint32_t b0, b1, b2, b3;
                LDSM_X4(b0, b1, b2, b3,
                        wb + b_lofs + (uint32_t)(nb2 * 16 * HSTR * 2 + kk * 32));
                #pragma unroll
                for (int mb = 0; mb < 2; mb++) {
                    mma_f16(cC[mb][2 * nb2],     ax[mb][kk], b0, b1);
                    mma_f16(cC[mb][2 * nb2 + 1], ax[mb][kk], b2, b3);
                }
            }
        }

        #pragma unroll
        for (int nb = 0; nb < 8; nb++) {
            float2 bb = *(const float2*)&bias[h * 64 + nb * 8 + 2 * t];
            #pragma unroll
            for (int mb = 0; mb < 2; mb++) {
                int rl = r0 + mb * 16 + g;
                __half2 h0 = __floats2half2_rn((cC[mb][nb][0] + bb.x) * sc,
                                               (cC[mb][nb][1] + bb.y) * sc);
                __half2 h1 = __floats2half2_rn((cC[mb][nb][2] + bb.x) * sc,
                                               (cC[mb][nb][3] + bb.y) * sc);
                *(__half2*)&dst[((size_t)bh * NS + s0 + rl) * 64 + nb * 8 + 2 * t]     = h0;
                *(__half2*)&dst[((size_t)bh * NS + s0 + rl + 8) * 64 + nb * 8 + 2 * t] = h1;
            }
        }
    }
}

// ---------------------------------------------------------------------------
// Kernel 2: fp16 flash attention, chunk-scheduled (R10 core) with FUSED
// combine: full-coverage segments write normalized output directly; split
// tiles use a per-tile arrival flag — the second-finishing producer reads
// both partial slices, writes the final output, and resets the flag.
// ---------------------------------------------------------------------------
constexpr int TILE_H = 64 * HSTR;
constexpr uint32_t KBUF_B = TILE_H * 2;           // 9216 bytes per buffer
constexpr size_t ATTN_SMEM = (size_t)4 * KBUF_B;  // 36864 B

__global__ __launch_bounds__(128, 3) void attn_mma(float* __restrict__ out)
{
    extern __shared__ __half sm[];
    __shared__ int s_old;
    const uint32_t smb = smem_u32(sm);

    const int tid  = threadIdx.x;
    const int lane = tid & 31;
    const int w    = tid >> 5;
    const int g    = lane >> 2;
    const int t    = lane & 3;
    const int r0   = w * 32;

    const uint32_t a_lofs =
        (uint32_t)(((r0 + (lane & 15)) * HSTR + 8 * (lane >> 4)) * 2);
    const uint32_t k_lofs =
        (uint32_t)(((8 * (lane >> 4) + (lane & 7)) * HSTR + 8 * ((lane >> 3) & 1)) * 2);
    const uint32_t v_lofs =
        (uint32_t)(((8 * ((lane >> 3) & 1) + (lane & 7)) * HSTR + 8 * (lane >> 4)) * 2);

    int u          = blockIdx.x * CHUNK;
    const int uend = min(u + CHUNK, UNITS);

    while (u < uend) {
        const int qt = u >> 5;
        const int k0 = u & 31;
        const int k1 = min(32, k0 + (uend - u));
        const int b  = qt >> 8;
        const int h  = (qt >> 4) & 15;
        const int qb = qt & 15;
        const int bh = b * NH + h;

        const __half* Qg = g_Q + ((size_t)bh * NS + (size_t)qb * 128) * DH;
        const __half* Kg = g_K + (size_t)bh * NS * DH;
        const __half* Vg = g_V + (size_t)bh * NS * DH;

        __syncthreads();   // previous segment fully done with smem

        #pragma unroll
        for (int it = 0; it < 8; it++) {
            int i = it * 128 + tid;
            int r = i >> 3, c8 = i & 7;
            *(uint4*)&sm[r * HSTR + c8 * 8] = *(const uint4*)&Qg[r * 64 + c8 * 8];
        }
        __syncthreads();

        uint32_t aq[2][4][4];
        #pragma unroll
        for (int mb = 0; mb < 2; mb++)
            #pragma unroll
            for (int kk = 0; kk < 4; kk++)
                LDSM_X4(aq[mb][kk][0], aq[mb][kk][1], aq[mb][kk][2], aq[mb][kk][3],
                        smb + a_lofs + (uint32_t)(mb * 16 * HSTR * 2 + kk * 32));
        __syncthreads();   // all aq reads done before cp.async overwrites

        {
            const uint32_t cur = (uint32_t)(k0 & 1);
            const __half* Ksrc = Kg + (size_t)k0 * 64 * DH;
            const __half* Vsrc = Vg + (size_t)k0 * 64 * DH;
            #pragma unroll
            for (int it = 0; it < 4; it++) {
                int i = it * 128 + tid;
                int r = i >> 3, c8 = i & 7;
                uint32_t off = (uint32_t)(r * HSTR + c8 * 8) * 2;
                CP_ASYNC16(smb + cur * KBUF_B + off,
                           (const char*)(Ksrc + r * 64 + c8 * 8));
                CP_ASYNC16(smb + 2 * KBUF_B + cur * KBUF_B + off,
                           (const char*)(Vsrc + r * 64 + c8 * 8));
            }
            CP_COMMIT();
        }

        float cO[2][8][4];
        float lf[2][2];
        #pragma unroll
        for (int mb = 0; mb < 2; mb++) {
            #pragma unroll
            for (int nb = 0; nb < 8; nb++)
                #pragma unroll
                for (int r = 0; r < 4; r++) cO[mb][nb][r] = 0.0f;
            lf[mb][0] = 0.0f;
            lf[mb][1] = 0.0f;
        }

        for (int kt = k0; kt < k1; kt++) {
            const uint32_t cur = (uint32_t)(kt & 1);
            CP_WAIT0();
            __syncthreads();

            if (kt + 1 < k1) {
                const __half* Ksrc = Kg + (size_t)(kt + 1) * 64 * DH;
                const __half* Vsrc = Vg + (size_t)(kt + 1) * 64 * DH;
                const uint32_t nxt = cur ^ 1u;
                #pragma unroll
                for (int it = 0; it < 4; it++) {
                    int i = it * 128 + tid;
                    int r = i >> 3, c8 = i & 7;
                    uint32_t off = (uint32_t)(r * HSTR + c8 * 8) * 2;
                    CP_ASYNC16(smb + nxt * KBUF_B + off,
                               (const char*)(Ksrc + r * 64 + c8 * 8));
                    CP_ASYNC16(smb + 2 * KBUF_B + nxt * KBUF_B + off,
                               (const char*)(Vsrc + r * 64 + c8 * 8));
                }
                CP_COMMIT();
            }

            const uint32_t kaddr = smb + cur * KBUF_B + k_lofs;
            const uint32_t vaddr = smb + 2 * KBUF_B + cur * KBUF_B + v_lofs;

            uint32_t ap[2][4][4];
            #pragma unroll
            for (int nb2 = 0; nb2 < 4; nb2++) {
                float cS[2][2][4];
                #pragma unroll
                for (int mb = 0; mb < 2; mb++)
                    #pragma unroll
                    for (int n = 0; n < 2; n++)
                        #pragma unroll
                        for (int r = 0; r < 4; r++) cS[mb][n][r] = 0.0f;

                #pragma unroll
                for (int kk = 0; kk < 4; kk++) {
                    uint32_t b0, b1, b2, b3;
                    LDSM_X4(b0, b1, b2, b3,
                            kaddr + (uint32_t)(nb2 * 16 * HSTR * 2 + kk * 32));
                    #pragma unroll
                    for (int mb = 0; mb < 2; mb++) {
                        mma_f16(cS[mb][0], aq[mb][kk], b0, b1);
                        mma_f16(cS[mb][1], aq[mb][kk], b2, b3);
                    }
                }
                #pragma unroll
                for (int mb = 0; mb < 2; mb++) {
                    ap[mb][nb2][0] = ex2_f16x2(pack_h2(cS[mb][0][0], cS[mb][0][1]));
                    ap[mb][nb2][1] = ex2_f16x2(pack_h2(cS[mb][0][2], cS[mb][0][3]));
                    ap[mb][nb2][2] = ex2_f16x2(pack_h2(cS[mb][1][0], cS[mb][1][1]));
                    ap[mb][nb2][3] = ex2_f16x2(pack_h2(cS[mb][1][2], cS[mb][1][3]));
                }
            }

            #pragma unroll
            for (int kk = 0; kk < 4; kk++) {
                #pragma unroll
                for (int nb2 = 0; nb2 < 4; nb2++) {
                    uint32_t b0, b1, b2, b3;
                    LDSM_X4_T(b0, b1, b2, b3,
                              vaddr + (uint32_t)(kk * 16 * HSTR * 2 + nb2 * 32));
                    #pragma unroll
                    for (int mb = 0; mb < 2; mb++) {
                        mma_f16(cO[mb][2 * nb2],     ap[mb][kk], b0, b1);
                        mma_f16(cO[mb][2 * nb2 + 1], ap[mb][kk], b2, b3);
                    }
                }
            }

            #pragma unroll
            for (int mb = 0; mb < 2; mb++) {
                __half2 sg = __hadd2(as_h2(ap[mb][0][0]), as_h2(ap[mb][0][2]));
                __half2 sh = __hadd2(as_h2(ap[mb][0][1]), as_h2(ap[mb][0][3]));
                #pragma unroll
                for (int kk = 1; kk < 4; kk++) {
                    sg = __hadd2(sg, __hadd2(as_h2(ap[mb][kk][0]), as_h2(ap[mb][kk][2])));
                    sh = __hadd2(sh, __hadd2(as_h2(ap[mb][kk][1]), as_h2(ap[mb][kk][3])));
                }
                float2 fg = __half22float2(sg);
                float2 fh = __half22float2(sh);
                lf[mb][0] += fg.x + fg.y;
                lf[mb][1] += fh.x + fh.y;
            }
        }

        // ---- segment epilogue ----
        #pragma unroll
        for (int mb = 0; mb < 2; mb++)
            #pragma unroll
            for (int rr = 0; rr < 2; rr++) {
                lf[mb][rr] += __shfl_xor_sync(0xffffffffu, lf[mb][rr], 1);
                lf[mb][rr] += __shfl_xor_sync(0xffffffffu, lf[mb][rr], 2);
            }

        float* outq = out + ((size_t)(b * NS) + (size_t)qb * 128) * ND + h * DH;

        if (k0 == 0 && k1 == 32) {
            // full coverage: normalize in registers, write final output
            #pragma unroll
            for (int mb = 0; mb < 2; mb++) {
                const float inv0 = 1.0f / lf[mb][0];
                const float inv1 = 1.0f / lf[mb][1];
                const int rl = r0 + mb * 16 + g;
                #pragma unroll
                for (int nb = 0; nb < 8; nb++) {
                    *(float2*)&outq[(size_t)rl * ND + nb * 8 + 2 * t] =
                        make_float2(cO[mb][nb][0] * inv0, cO[mb][nb][1] * inv0);
                    *(float2*)&outq[(size_t)(rl + 8) * ND + nb * 8 + 2 * t] =
                        make_float2(cO[mb][nb][2] * inv1, cO[mb][nb][3] * inv1);
                }
            }
        } else {
            // split tile: write partial slice, then last-arriver combines
            const int slice = (k0 == 0) ? 0 : 1;
            float* Os = g_pO[slice][qt];
            float* Ls = g_pL[slice][qt];
            #pragma unroll
            for (int mb = 0; mb < 2; mb++) {
                const int rl = r0 + mb * 16 + g;
                #pragma unroll
                for (int nb = 0; nb < 8; nb++) {
                    *(float2*)&Os[rl * 64 + nb * 8 + 2 * t] =
                        make_float2(cO[mb][nb][0], cO[mb][nb][1]);
                    *(float2*)&Os[(rl + 8) * 64 + nb * 8 + 2 * t] =
                        make_float2(cO[mb][nb][2], cO[mb][nb][3]);
                }
                if (t == 0) {
                    Ls[rl]     = lf[mb][0];
                    Ls[rl + 8] = lf[mb][1];
                }
            }
            __threadfence();
            if (tid == 0) s_old = atomicAdd(&g_flag[qt], 1);
            __syncthreads();
            if (s_old == 1) {
                // we are second: both slices visible (each producer fenced
                // before its arrive). Combine and write final output.
                const int row = tid;   // 128 threads = 128 rows
                float l = g_pL[0][qt][row] + g_pL[1][qt][row];
                const float inv = 1.0f / l;
                const float* O0 = &g_pO[0][qt][row * 64];
                const float* O1 = &g_pO[1][qt][row * 64];
                float* od = outq + (size_t)row * ND;
                #pragma unroll
                for (int c4 = 0; c4 < 16; c4++) {
                    float4 a4 = *(const float4*)&O0[c4 * 4];
                    float4 b4 = *(const float4*)&O1[c4 * 4];
                    *(float4*)&od[c4 * 4] = make_float4(
                        (a4.x + b4.x) * inv, (a4.y + b4.y) * inv,
                        (a4.z + b4.z) * inv, (a4.w + b4.w) * inv);
                }
                __syncthreads();
                if (tid == 0) g_flag[qt] = 0;   // reset for next graph replay
            }
        }

        u += k1 - k0;
    }
}

// ---------------------------------------------------------------------------
extern "C" void kernel_launch(void* const* d_in, const int* in_sizes, int n_in,
                              void* d_out, int out_size)
{
    const float* seqs = (const float*)d_in[0];
    const float* Wq   = (const float*)d_in[1];
    const float* bq   = (const float*)d_in[2];
    const float* Wk   = (const float*)d_in[3];
    const float* bk   = (const float*)d_in[4];
    const float* Wv   = (const float*)d_in[5];
    const float* bv   = (const float*)d_in[6];
    float* out = (float*)d_out;
    (void)in_sizes; (void)n_in; (void)out_size;

    proj_kernel<<<dim3(NB * NS / 128, NH), 128>>>(seqs, Wq, bq, Wk, bk, Wv, bv);

    cudaFuncSetAttribute(attn_mma, cudaFuncAttributeMaxDynamicSharedMemorySize,
                         (int)ATTN_SMEM);
    attn_mma<<<GRID_ATTN, 128, ATTN_SMEM>>>(out);
}

// round 16
// speedup vs baseline: 1.0696x; 1.0696x over previous
#include <cuda_runtime.h>
#include <cuda_fp16.h>
#include <math.h>
#include <stdint.h>

// Problem constants
constexpr int NB = 2;
constexpr int NS = 2048;
constexpr int ND = 1024;
constexpr int NH = 16;
constexpr int DH = 64;

// Chunked scheduling over (q-tile, 64-key-tile) units  [R10 winner]
constexpr int NQT   = NB * NH * (NS / 128);   // 512 q-tiles
constexpr int NT    = NS / 64;                // 32 key tiles per q-tile
constexpr int UNITS = NQT * NT;               // 16384
constexpr int GRID_ATTN = 444;                // 3 CTAs/SM x 148 SMs = one wave
constexpr int CHUNK = (UNITS + GRID_ATTN - 1) / GRID_ATTN;  // 37 (>=32 -> <=2 slices/tile)

// log2(e) folded into Q pre-scale: softmax exp(s) == ex2(s * log2e)
constexpr float QSCALE = 0.125f * 1.4426950408889634f;

// Scratch: projected Q/K/V in fp16, [b,h,s,e]
__device__ __half g_Q[(size_t)NB * NH * NS * DH];
__device__ __half g_K[(size_t)NB * NH * NS * DH];
__device__ __half g_V[(size_t)NB * NH * NS * DH];
// Partial (unnormalized) attention outputs: [slice][qt][row][col] + row sums
__device__ float g_pO[2][NQT][128 * 64];
__device__ float g_pL[2][NQT][128];

__device__ __forceinline__ uint32_t smem_u32(const void* p) {
    uint32_t a;
    asm("{ .reg .u64 t; cvta.to.shared.u64 t, %1; cvt.u32.u64 %0, t; }"
        : "=r"(a) : "l"(p));
    return a;
}
__device__ __forceinline__ void mma_f16(float c[4], const uint32_t a[4],
                                        uint32_t b0, uint32_t b1) {
    asm volatile(
        "mma.sync.aligned.m16n8k16.row.col.f32.f16.f16.f32 "
        "{%0,%1,%2,%3}, {%4,%5,%6,%7}, {%8,%9}, {%0,%1,%2,%3};"
        : "+f"(c[0]), "+f"(c[1]), "+f"(c[2]), "+f"(c[3])
        : "r"(a[0]), "r"(a[1]), "r"(a[2]), "r"(a[3]), "r"(b0), "r"(b1));
}
#define LDSM_X4(r0, r1, r2, r3, addr) \
    asm volatile("ldmatrix.sync.aligned.m8n8.x4.shared.b16 {%0,%1,%2,%3}, [%4];" \
                 : "=r"(r0), "=r"(r1), "=r"(r2), "=r"(r3) : "r"(addr))
#define LDSM_X4_T(r0, r1, r2, r3, addr) \
    asm volatile("ldmatrix.sync.aligned.m8n8.x4.trans.shared.b16 {%0,%1,%2,%3}, [%4];" \
                 : "=r"(r0), "=r"(r1), "=r"(r2), "=r"(r3) : "r"(addr))
#define CP_ASYNC16(dst, src) \
    asm volatile("cp.async.cg.shared.global [%0], [%1], 16;" :: "r"(dst), "l"(src))
#define CP_COMMIT() asm volatile("cp.async.commit_group;")
#define CP_WAIT0()  asm volatile("cp.async.wait_group 0;")
#define CP_WAIT1()  asm volatile("cp.async.wait_group 1;")

__device__ __forceinline__ uint32_t ex2_f16x2(uint32_t x) {
    uint32_t r;
    asm("ex2.approx.f16x2 %0, %1;" : "=r"(r) : "r"(x));
    return r;
}
__device__ __forceinline__ uint32_t pack_h2(float a, float b) {
    __half2 h = __floats2half2_rn(a, b);
    return *(uint32_t*)&h;
}
__device__ __forceinline__ __half2 as_h2(uint32_t x) { return *(__half2*)&x; }

constexpr int HSTR = 72;  // halves per smem row (144B): conflict-free ldmatrix

// ---------------------------------------------------------------------------
// Kernel 1: per-head QKV projection on fp16 mma, W-load pipelined.
// CTA = 128 threads, 128 rows. W(m+1) cp.async'd (fp32 stage, double-buffered)
// while GEMM(m) runs; convert fp32->fp16 from stage into ws between GEMMs.
// smem layout (dynamic): xs fp16[128*HSTR] | ws fp16[64*HSTR] | stage fp32[2][4096]
// ---------------------------------------------------------------------------
constexpr uint32_t PJ_XS  = 0;                       // 18432 B
constexpr uint32_t PJ_WS  = PJ_XS + 128 * HSTR * 2;  //  9216 B
constexpr uint32_t PJ_ST0 = PJ_WS + 64 * HSTR * 2;   // 16384 B
constexpr uint32_t PJ_ST1 = PJ_ST0 + 16384;          // 16384 B
constexpr size_t PROJ_SMEM = PJ_ST1 + 16384;         // 60416 B

__global__ __launch_bounds__(128) void proj_kernel(
    const float* __restrict__ seqs,
    const float* __restrict__ Wq, const float* __restrict__ bq,
    const float* __restrict__ Wk, const float* __restrict__ bk,
    const float* __restrict__ Wv, const float* __restrict__ bv)
{
    extern __shared__ char psm[];
    __half* xs = (__half*)(psm + PJ_XS);
    __half* ws = (__half*)(psm + PJ_WS);
    const uint32_t smb = smem_u32(psm);

    const int tid  = threadIdx.x;
    const int lane = tid & 31;
    const int w    = tid >> 5;
    const int g    = lane >> 2;
    const int t    = lane & 3;
    const int r0   = w * 32;

    const int h   = blockIdx.y;
    const int gr0 = blockIdx.x * 128;
    const int b   = gr0 / NS;
    const int s0  = gr0 - b * NS;
    const int bh  = b * NH + h;

    const float* Wm[3] = {Wq, Wk, Wv};

    // ---- kick off cp.async of W0 into stage0 FIRST (overlaps x load) ----
    #pragma unroll
    for (int it = 0; it < 8; it++) {
        int f4 = it * 128 + tid;   // 1024 float4s = 16 KB
        CP_ASYNC16(smb + PJ_ST0 + (uint32_t)f4 * 16,
                   (const char*)(Wm[0] + h * 4096 + f4 * 4));
    }
    CP_COMMIT();

    // ---- load x tile (fp32 -> fp16) while W0 streams in ----
    #pragma unroll
    for (int it = 0; it < 16; it++) {
        int i = it * 128 + tid;
        int r = i >> 4, c4 = i & 15;
        float4 f = *(const float4*)&seqs[(size_t)(gr0 + r) * ND + h * 64 + c4 * 4];
        *(uint32_t*)&xs[r * HSTR + c4 * 4]     = pack_h2(f.x, f.y);
        *(uint32_t*)&xs[r * HSTR + c4 * 4 + 2] = pack_h2(f.z, f.w);
    }
    __syncthreads();

    const uint32_t xb = smb + PJ_XS;
    const uint32_t wb = smb + PJ_WS;
    const uint32_t a_lofs =
        (uint32_t)(((r0 + (lane & 15)) * HSTR + 8 * (lane >> 4)) * 2);
    const uint32_t b_lofs =
        (uint32_t)(((8 * (lane >> 4) + (lane & 7)) * HSTR + 8 * ((lane >> 3) & 1)) * 2);

    uint32_t ax[2][4][4];
    #pragma unroll
    for (int mb = 0; mb < 2; mb++)
        #pragma unroll
        for (int kk = 0; kk < 4; kk++)
            LDSM_X4(ax[mb][kk][0], ax[mb][kk][1], ax[mb][kk][2], ax[mb][kk][3],
                    xb + a_lofs + (uint32_t)(mb * 16 * HSTR * 2 + kk * 32));

    #pragma unroll
    for (int m = 0; m < 3; m++) {
        const float* bias = (m == 0) ? bq : ((m == 1) ? bk : bv);
        __half* dst       = (m == 0) ? g_Q : ((m == 1) ? g_K : g_V);
        const float sc    = (m == 0) ? QSCALE : 1.0f;
        const float* stage =
            (const float*)(psm + ((m & 1) ? PJ_ST1 : PJ_ST0));

        // prefetch W(m+1) into the other stage buffer, then wait for W(m)
        if (m + 1 < 3) {
            const uint32_t stn = (m & 1) ? PJ_ST0 : PJ_ST1;
            #pragma unroll
            for (int it = 0; it < 8; it++) {
                int f4 = it * 128 + tid;
                CP_ASYNC16(smb + stn + (uint32_t)f4 * 16,
                           (const char*)(Wm[m + 1] + h * 4096 + f4 * 4));
            }
            CP_COMMIT();
            CP_WAIT1();   // oldest group (W(m)) complete
        } else {
            CP_WAIT0();   // W2 complete
        }
        __syncthreads();  // stage ready for all; previous GEMM done with ws

        // convert stage fp32 -> ws fp16 (coalesced, conflict-free)
        #pragma unroll
        for (int it = 0; it < 8; it++) {
            int i = it * 512 + tid * 4;   // 4096 floats total
            int r = i >> 6, c4 = (i & 63) >> 2;
            float4 f = *(const float4*)&stage[i];
            *(uint32_t*)&ws[r * HSTR + c4 * 4]     = pack_h2(f.x, f.y);
            *(uint32_t*)&ws[r * HSTR + c4 * 4 + 2] = pack_h2(f.z, f.w);
        }
        __syncthreads();

        float cC[2][8][4];
        #pragma unroll
        for (int mb = 0; mb < 2; mb++)
            #pragma unroll
            for (int nb = 0; nb < 8; nb++)
                #pragma unroll
                for (int r = 0; r < 4; r++) cC[mb][nb][r] = 0.0f;

        #pragma unroll
        for (int kk = 0; kk < 4; kk++) {
            #pragma unroll
            for (int nb2 = 0; nb2 < 4; nb2++) {
                uint32_t b0, b1, b2, b3;
                LDSM_X4(b0, b1, b2, b3,
                        wb + b_lofs + (uint32_t)(nb2 * 16 * HSTR * 2 + kk * 32));
                #pragma unroll
                for (int mb = 0; mb < 2; mb++) {
                    mma_f16(cC[mb][2 * nb2],     ax[mb][kk], b0, b1);
                    mma_f16(cC[mb][2 * nb2 + 1], ax[mb][kk], b2, b3);
                }
            }
        }

        #pragma unroll
        for (int nb = 0; nb < 8; nb++) {
            float2 bb = *(const float2*)&bias[h * 64 + nb * 8 + 2 * t];
            #pragma unroll
            for (int mb = 0; mb < 2; mb++) {
                int rl = r0 + mb * 16 + g;
                __half2 h0 = __floats2half2_rn((cC[mb][nb][0] + bb.x) * sc,
                                               (cC[mb][nb][1] + bb.y) * sc);
                __half2 h1 = __floats2half2_rn((cC[mb][nb][2] + bb.x) * sc,
                                               (cC[mb][nb][3] + bb.y) * sc);
                *(__half2*)&dst[((size_t)bh * NS + s0 + rl) * 64 + nb * 8 + 2 * t]     = h0;
                *(__half2*)&dst[((size_t)bh * NS + s0 + rl + 8) * 64 + nb * 8 + 2 * t] = h1;
            }
        }
    }
}

// ---------------------------------------------------------------------------
// Kernel 2: fp16 flash attention, chunk-scheduled (R10 winner, unchanged).
// ---------------------------------------------------------------------------
constexpr int TILE_H = 64 * HSTR;
constexpr uint32_t KBUF_B = TILE_H * 2;           // 9216 bytes per buffer
constexpr size_t ATTN_SMEM = (size_t)4 * KBUF_B;  // 36864 B

__global__ __launch_bounds__(128, 3) void attn_mma()
{
    extern __shared__ __half sm[];
    const uint32_t smb = smem_u32(sm);

    const int tid  = threadIdx.x;
    const int lane = tid & 31;
    const int w    = tid >> 5;
    const int g    = lane >> 2;
    const int t    = lane & 3;
    const int r0   = w * 32;

    const uint32_t a_lofs =
        (uint32_t)(((r0 + (lane & 15)) * HSTR + 8 * (lane >> 4)) * 2);
    const uint32_t k_lofs =
        (uint32_t)(((8 * (lane >> 4) + (lane & 7)) * HSTR + 8 * ((lane >> 3) & 1)) * 2);
    const uint32_t v_lofs =
        (uint32_t)(((8 * ((lane >> 3) & 1) + (lane & 7)) * HSTR + 8 * (lane >> 4)) * 2);

    int u          = blockIdx.x * CHUNK;
    const int uend = min(u + CHUNK, UNITS);

    while (u < uend) {
        const int qt = u >> 5;
        const int k0 = u & 31;
        const int k1 = min(32, k0 + (uend - u));
        const int b  = qt >> 8;
        const int h  = (qt >> 4) & 15;
        const int qb = qt & 15;
        const int bh = b * NH + h;

        const __half* Qg = g_Q + ((size_t)bh * NS + (size_t)qb * 128) * DH;
        const __half* Kg = g_K + (size_t)bh * NS * DH;
        const __half* Vg = g_V + (size_t)bh * NS * DH;

        __syncthreads();   // previous segment fully done with smem

        #pragma unroll
        for (int it = 0; it < 8; it++) {
            int i = it * 128 + tid;
            int r = i >> 3, c8 = i & 7;
            *(uint4*)&sm[r * HSTR + c8 * 8] = *(const uint4*)&Qg[r * 64 + c8 * 8];
        }
        __syncthreads();

        uint32_t aq[2][4][4];
        #pragma unroll
        for (int mb = 0; mb < 2; mb++)
            #pragma unroll
            for (int kk = 0; kk < 4; kk++)
                LDSM_X4(aq[mb][kk][0], aq[mb][kk][1], aq[mb][kk][2], aq[mb][kk][3],
                        smb + a_lofs + (uint32_t)(mb * 16 * HSTR * 2 + kk * 32));
        __syncthreads();   // all aq reads done before cp.async overwrites

        {
            const uint32_t cur = (uint32_t)(k0 & 1);
            const __half* Ksrc = Kg + (size_t)k0 * 64 * DH;
            const __half* Vsrc = Vg + (size_t)k0 * 64 * DH;
            #pragma unroll
            for (int it = 0; it < 4; it++) {
                int i = it * 128 + tid;
                int r = i >> 3, c8 = i & 7;
                uint32_t off = (uint32_t)(r * HSTR + c8 * 8) * 2;
                CP_ASYNC16(smb + cur * KBUF_B + off,
                           (const char*)(Ksrc + r * 64 + c8 * 8));
                CP_ASYNC16(smb + 2 * KBUF_B + cur * KBUF_B + off,
                           (const char*)(Vsrc + r * 64 + c8 * 8));
            }
            CP_COMMIT();
        }

        float cO[2][8][4];
        float lf[2][2];
        #pragma unroll
        for (int mb = 0; mb < 2; mb++) {
            #pragma unroll
            for (int nb = 0; nb < 8; nb++)
                #pragma unroll
                for (int r = 0; r < 4; r++) cO[mb][nb][r] = 0.0f;
            lf[mb][0] = 0.0f;
            lf[mb][1] = 0.0f;
        }

        for (int kt = k0; kt < k1; kt++) {
            const uint32_t cur = (uint32_t)(kt & 1);
            CP_WAIT0();
            __syncthreads();

            if (kt + 1 < k1) {
                const __half* Ksrc = Kg + (size_t)(kt + 1) * 64 * DH;
                const __half* Vsrc = Vg + (size_t)(kt + 1) * 64 * DH;
                const uint32_t nxt = cur ^ 1u;
                #pragma unroll
                for (int it = 0; it < 4; it++) {
                    int i = it * 128 + tid;
                    int r = i >> 3, c8 = i & 7;
                    uint32_t off = (uint32_t)(r * HSTR + c8 * 8) * 2;
                    CP_ASYNC16(smb + nxt * KBUF_B + off,
                               (const char*)(Ksrc + r * 64 + c8 * 8));
                    CP_ASYNC16(smb + 2 * KBUF_B + nxt * KBUF_B + off,
                               (const char*)(Vsrc + r * 64 + c8 * 8));
                }
                CP_COMMIT();
            }

            const uint32_t kaddr = smb + cur * KBUF_B + k_lofs;
            const uint32_t vaddr = smb + 2 * KBUF_B + cur * KBUF_B + v_lofs;

            uint32_t ap[2][4][4];
            #pragma unroll
            for (int nb2 = 0; nb2 < 4; nb2++) {
                float cS[2][2][4];
                #pragma unroll
                for (int mb = 0; mb < 2; mb++)
                    #pragma unroll
                    for (int n = 0; n < 2; n++)
                        #pragma unroll
                        for (int r = 0; r < 4; r++) cS[mb][n][r] = 0.0f;

                #pragma unroll
                for (int kk = 0; kk < 4; kk++) {
                    uint32_t b0, b1, b2, b3;
                    LDSM_X4(b0, b1, b2, b3,
                            kaddr + (uint32_t)(nb2 * 16 * HSTR * 2 + kk * 32));
                    #pragma unroll
                    for (int mb = 0; mb < 2; mb++) {
                        mma_f16(cS[mb][0], aq[mb][kk], b0, b1);
                        mma_f16(cS[mb][1], aq[mb][kk], b2, b3);
                    }
                }
                #pragma unroll
                for (int mb = 0; mb < 2; mb++) {
                    ap[mb][nb2][0] = ex2_f16x2(pack_h2(cS[mb][0][0], cS[mb][0][1]));
                    ap[mb][nb2][1] = ex2_f16x2(pack_h2(cS[mb][0][2], cS[mb][0][3]));
                    ap[mb][nb2][2] = ex2_f16x2(pack_h2(cS[mb][1][0], cS[mb][1][1]));
                    ap[mb][nb2][3] = ex2_f16x2(pack_h2(cS[mb][1][2], cS[mb][1][3]));
                }
            }

            #pragma unroll
            for (int kk = 0; kk < 4; kk++) {
                #pragma unroll
                for (int nb2 = 0; nb2 < 4; nb2++) {
                    uint32_t b0, b1, b2, b3;
                    LDSM_X4_T(b0, b1, b2, b3,
                              vaddr + (uint32_t)(kk * 16 * HSTR * 2 + nb2 * 32));
                    #pragma unroll
                    for (int mb = 0; mb < 2; mb++) {
                        mma_f16(cO[mb][2 * nb2],     ap[mb][kk], b0, b1);
                        mma_f16(cO[mb][2 * nb2 + 1], ap[mb][kk], b2, b3);
                    }
                }
            }

            #pragma unroll
            for (int mb = 0; mb < 2; mb++) {
                __half2 sg = __hadd2(as_h2(ap[mb][0][0]), as_h2(ap[mb][0][2]));
                __half2 sh = __hadd2(as_h2(ap[mb][0][1]), as_h2(ap[mb][0][3]));
                #pragma unroll
                for (int kk = 1; kk < 4; kk++) {
                    sg = __hadd2(sg, __hadd2(as_h2(ap[mb][kk][0]), as_h2(ap[mb][kk][2])));
                    sh = __hadd2(sh, __hadd2(as_h2(ap[mb][kk][1]), as_h2(ap[mb][kk][3])));
                }
                float2 fg = __half22float2(sg);
                float2 fh = __half22float2(sh);
                lf[mb][0] += fg.x + fg.y;
                lf[mb][1] += fh.x + fh.y;
            }
        }

        #pragma unroll
        for (int mb = 0; mb < 2; mb++)
            #pragma unroll
            for (int rr = 0; rr < 2; rr++) {
                lf[mb][rr] += __shfl_xor_sync(0xffffffffu, lf[mb][rr], 1);
                lf[mb][rr] += __shfl_xor_sync(0xffffffffu, lf[mb][rr], 2);
            }

        const int slice = (k0 == 0) ? 0 : 1;
        float* Os = g_pO[slice][qt];
        float* Ls = g_pL[slice][qt];
        #pragma unroll
        for (int mb = 0; mb < 2; mb++) {
            const int rl = r0 + mb * 16 + g;
            #pragma unroll
            for (int nb = 0; nb < 8; nb++) {
                *(float2*)&Os[rl * 64 + nb * 8 + 2 * t] =
                    make_float2(cO[mb][nb][0], cO[mb][nb][1]);
                *(float2*)&Os[(rl + 8) * 64 + nb * 8 + 2 * t] =
                    make_float2(cO[mb][nb][2], cO[mb][nb][3]);
            }
            if (t == 0) {
                Ls[rl]     = lf[mb][0];
                Ls[rl + 8] = lf[mb][1];
            }
        }

        u += k1 - k0;
    }
}

// ---------------------------------------------------------------------------
// Kernel 3: combine partial slices and normalize into out (float4-wide).
// ---------------------------------------------------------------------------
__global__ __launch_bounds__(256) void combine_kernel(float* __restrict__ out)
{
    const int idx  = blockIdx.x * 256 + threadIdx.x;   // one float4 each
    const int col4 = idx & 15;
    const int rowg = idx >> 4;
    const int qt   = rowg >> 7;
    const int row  = rowg & 127;

    const int start = qt * 32;
    const int i0    = start / CHUNK + 1;
    const bool split = (i0 * CHUNK) < (start + 32);

    float l = g_pL[0][qt][row];
    float4 s = *(const float4*)&g_pO[0][qt][row * 64 + 4 * col4];
    if (split) {
        l += g_pL[1][qt][row];
        float4 s1 = *(const float4*)&g_pO[1][qt][row * 64 + 4 * col4];
        s.x += s1.x; s.y += s1.y; s.z += s1.z; s.w += s1.w;
    }
    const float inv = 1.0f / l;

    const int b  = qt >> 8;
    const int h  = (qt >> 4) & 15;
    const int qb = qt & 15;
    float* o = out + ((size_t)b * NS + (size_t)qb * 128 + row) * ND + h * 64 + 4 * col4;
    *(float4*)o = make_float4(s.x * inv, s.y * inv, s.z * inv, s.w * inv);
}

// ---------------------------------------------------------------------------
extern "C" void kernel_launch(void* const* d_in, const int* in_sizes, int n_in,
                              void* d_out, int out_size)
{
    const float* seqs = (const float*)d_in[0];
    const float* Wq   = (const float*)d_in[1];
    const float* bq   = (const float*)d_in[2];
    const float* Wk   = (const float*)d_in[3];
    const float* bk   = (const float*)d_in[4];
    const float* Wv   = (const float*)d_in[5];
    const float* bv   = (const float*)d_in[6];
    float* out = (float*)d_out;
    (void)in_sizes; (void)n_in; (void)out_size;

    cudaFuncSetAttribute(proj_kernel, cudaFuncAttributeMaxDynamicSharedMemorySize,
                         (int)PROJ_SMEM);
    proj_kernel<<<dim3(NB * NS / 128, NH), 128, PROJ_SMEM>>>(
        seqs, Wq, bq, Wk, bk, Wv, bv);

    cudaFuncSetAttribute(attn_mma, cudaFuncAttributeMaxDynamicSharedMemorySize,
                         (int)ATTN_SMEM);
    attn_mma<<<GRID_ATTN, 128, ATTN_SMEM>>>();

    combine_kernel<<<(NQT * 128 * 16) / 256, 256>>>(out);
}

// round 17
// speedup vs baseline: 1.0754x; 1.0055x over previous
#include <cuda_runtime.h>
#include <cuda_fp16.h>
#include <math.h>
#include <stdint.h>

// Problem constants
constexpr int NB = 2;
constexpr int NS = 2048;
constexpr int ND = 1024;
constexpr int NH = 16;
constexpr int DH = 64;

// Chunked scheduling over (q-tile, 64-key-tile) units  [R10 winner]
constexpr int NQT   = NB * NH * (NS / 128);   // 512 q-tiles
constexpr int NT    = NS / 64;                // 32 key tiles per q-tile
constexpr int UNITS = NQT * NT;               // 16384
constexpr int GRID_ATTN = 444;                // 3 CTAs/SM x 148 SMs = one wave
constexpr int CHUNK = (UNITS + GRID_ATTN - 1) / GRID_ATTN;  // 37 (>=32 -> <=2 slices/tile)

// log2(e) folded into Q pre-scale: softmax exp(s) == ex2(s * log2e)
constexpr float QSCALE = 0.125f * 1.4426950408889634f;

// Scratch: projected Q/K/V in fp16, [b,h,s,e]
__device__ __half g_Q[(size_t)NB * NH * NS * DH];
__device__ __half g_K[(size_t)NB * NH * NS * DH];
__device__ __half g_V[(size_t)NB * NH * NS * DH];
// Partial (unnormalized) attention outputs: [slice][qt][row][col] + row sums
__device__ float g_pO[2][NQT][128 * 64];
__device__ float g_pL[2][NQT][128];

__device__ __forceinline__ uint32_t smem_u32(const void* p) {
    uint32_t a;
    asm("{ .reg .u64 t; cvta.to.shared.u64 t, %1; cvt.u32.u64 %0, t; }"
        : "=r"(a) : "l"(p));
    return a;
}
__device__ __forceinline__ void mma_f16(float c[4], const uint32_t a[4],
                                        uint32_t b0, uint32_t b1) {
    asm volatile(
        "mma.sync.aligned.m16n8k16.row.col.f32.f16.f16.f32 "
        "{%0,%1,%2,%3}, {%4,%5,%6,%7}, {%8,%9}, {%0,%1,%2,%3};"
        : "+f"(c[0]), "+f"(c[1]), "+f"(c[2]), "+f"(c[3])
        : "r"(a[0]), "r"(a[1]), "r"(a[2]), "r"(a[3]), "r"(b0), "r"(b1));
}
#define LDSM_X4(r0, r1, r2, r3, addr) \
    asm volatile("ldmatrix.sync.aligned.m8n8.x4.shared.b16 {%0,%1,%2,%3}, [%4];" \
                 : "=r"(r0), "=r"(r1), "=r"(r2), "=r"(r3) : "r"(addr))
#define LDSM_X4_T(r0, r1, r2, r3, addr) \
    asm volatile("ldmatrix.sync.aligned.m8n8.x4.trans.shared.b16 {%0,%1,%2,%3}, [%4];" \
                 : "=r"(r0), "=r"(r1), "=r"(r2), "=r"(r3) : "r"(addr))
#define CP_ASYNC16(dst, src) \
    asm volatile("cp.async.cg.shared.global [%0], [%1], 16;" :: "r"(dst), "l"(src))
#define CP_COMMIT() asm volatile("cp.async.commit_group;")
#define CP_WAIT0()  asm volatile("cp.async.wait_group 0;")

__device__ __forceinline__ uint32_t ex2_f16x2(uint32_t x) {
    uint32_t r;
    asm("ex2.approx.f16x2 %0, %1;" : "=r"(r) : "r"(x));
    return r;
}
__device__ __forceinline__ uint32_t pack_h2(float a, float b) {
    __half2 h = __floats2half2_rn(a, b);
    return *(uint32_t*)&h;
}
__device__ __forceinline__ __half2 as_h2(uint32_t x) { return *(__half2*)&x; }

constexpr int HSTR = 72;  // halves per smem row (144B): conflict-free ldmatrix

// ---------------------------------------------------------------------------
// Kernel 1: per-head QKV projection on fp16 mma (R10 serial version, best
// measured). CTA = 128 threads, 128 rows.
// ---------------------------------------------------------------------------
__global__ __launch_bounds__(128) void proj_kernel(
    const float* __restrict__ seqs,
    const float* __restrict__ Wq, const float* __restrict__ bq,
    const float* __restrict__ Wk, const float* __restrict__ bk,
    const float* __restrict__ Wv, const float* __restrict__ bv)
{
    __shared__ __half xs[128 * HSTR];
    __shared__ __half ws[64 * HSTR];

    const int tid  = threadIdx.x;
    const int lane = tid & 31;
    const int w    = tid >> 5;
    const int g    = lane >> 2;
    const int t    = lane & 3;
    const int r0   = w * 32;

    const int h   = blockIdx.y;
    const int gr0 = blockIdx.x * 128;
    const int b   = gr0 / NS;
    const int s0  = gr0 - b * NS;
    const int bh  = b * NH + h;

    #pragma unroll
    for (int it = 0; it < 16; it++) {
        int i = it * 128 + tid;
        int r = i >> 4, c4 = i & 15;
        float4 f = *(const float4*)&seqs[(size_t)(gr0 + r) * ND + h * 64 + c4 * 4];
        *(uint32_t*)&xs[r * HSTR + c4 * 4]     = pack_h2(f.x, f.y);
        *(uint32_t*)&xs[r * HSTR + c4 * 4 + 2] = pack_h2(f.z, f.w);
    }
    __syncthreads();

    const uint32_t xb = smem_u32(xs);
    const uint32_t wb = smem_u32(ws);
    const uint32_t a_lofs =
        (uint32_t)(((r0 + (lane & 15)) * HSTR + 8 * (lane >> 4)) * 2);
    const uint32_t b_lofs =
        (uint32_t)(((8 * (lane >> 4) + (lane & 7)) * HSTR + 8 * ((lane >> 3) & 1)) * 2);

    uint32_t ax[2][4][4];
    #pragma unroll
    for (int mb = 0; mb < 2; mb++)
        #pragma unroll
        for (int kk = 0; kk < 4; kk++)
            LDSM_X4(ax[mb][kk][0], ax[mb][kk][1], ax[mb][kk][2], ax[mb][kk][3],
                    xb + a_lofs + (uint32_t)(mb * 16 * HSTR * 2 + kk * 32));

    #pragma unroll
    for (int m = 0; m < 3; m++) {
        const float* W    = (m == 0) ? Wq : ((m == 1) ? Wk : Wv);
        const float* bias = (m == 0) ? bq : ((m == 1) ? bk : bv);
        __half* dst       = (m == 0) ? g_Q : ((m == 1) ? g_K : g_V);
        const float sc    = (m == 0) ? QSCALE : 1.0f;

        __syncthreads();
        #pragma unroll
        for (int it = 0; it < 8; it++) {
            int i = it * 128 + tid;
            int r = i >> 4, c4 = i & 15;
            float4 f = *(const float4*)&W[h * 4096 + r * 64 + c4 * 4];
            *(uint32_t*)&ws[r * HSTR + c4 * 4]     = pack_h2(f.x, f.y);
            *(uint32_t*)&ws[r * HSTR + c4 * 4 + 2] = pack_h2(f.z, f.w);
        }
        __syncthreads();

        float cC[2][8][4];
        #pragma unroll
        for (int mb = 0; mb < 2; mb++)
            #pragma unroll
            for (int nb = 0; nb < 8; nb++)
                #pragma unroll
                for (int r = 0; r < 4; r++) cC[mb][nb][r] = 0.0f;

        #pragma unroll
        for (int kk = 0; kk < 4; kk++) {
            #pragma unroll
            for (int nb2 = 0; nb2 < 4; nb2++) {
                uint32_t b0, b1, b2, b3;
                LDSM_X4(b0, b1, b2, b3,
                        wb + b_lofs + (uint32_t)(nb2 * 16 * HSTR * 2 + kk * 32));
                #pragma unroll
                for (int mb = 0; mb < 2; mb++) {
                    mma_f16(cC[mb][2 * nb2],     ax[mb][kk], b0, b1);
                    mma_f16(cC[mb][2 * nb2 + 1], ax[mb][kk], b2, b3);
                }
            }
        }

        #pragma unroll
        for (int nb = 0; nb < 8; nb++) {
            float2 bb = *(const float2*)&bias[h * 64 + nb * 8 + 2 * t];
            #pragma unroll
            for (int mb = 0; mb < 2; mb++) {
                int rl = r0 + mb * 16 + g;
                __half2 h0 = __floats2half2_rn((cC[mb][nb][0] + bb.x) * sc,
                                               (cC[mb][nb][1] + bb.y) * sc);
                __half2 h1 = __floats2half2_rn((cC[mb][nb][2] + bb.x) * sc,
                                               (cC[mb][nb][3] + bb.y) * sc);
                *(__half2*)&dst[((size_t)bh * NS + s0 + rl) * 64 + nb * 8 + 2 * t]     = h0;
                *(__half2*)&dst[((size_t)bh * NS + s0 + rl + 8) * 64 + nb * 8 + 2 * t] = h1;
            }
        }
    }
}

// ---------------------------------------------------------------------------
// Kernel 2: fp16 flash attention, chunk-scheduled (R10 core). Full-coverage
// segments (k0==0 && k1==32) normalize in registers and write out DIRECTLY
// (no partials, no fence); split tiles write partials for the combine pass.
// ---------------------------------------------------------------------------
constexpr int TILE_H = 64 * HSTR;
constexpr uint32_t KBUF_B = TILE_H * 2;           // 9216 bytes per buffer
constexpr size_t ATTN_SMEM = (size_t)4 * KBUF_B;  // 36864 B

__global__ __launch_bounds__(128, 3) void attn_mma(float* __restrict__ out)
{
    extern __shared__ __half sm[];
    const uint32_t smb = smem_u32(sm);

    const int tid  = threadIdx.x;
    const int lane = tid & 31;
    const int w    = tid >> 5;
    const int g    = lane >> 2;
    const int t    = lane & 3;
    const int r0   = w * 32;

    const uint32_t a_lofs =
        (uint32_t)(((r0 + (lane & 15)) * HSTR + 8 * (lane >> 4)) * 2);
    const uint32_t k_lofs =
        (uint32_t)(((8 * (lane >> 4) + (lane & 7)) * HSTR + 8 * ((lane >> 3) & 1)) * 2);
    const uint32_t v_lofs =
        (uint32_t)(((8 * ((lane >> 3) & 1) + (lane & 7)) * HSTR + 8 * (lane >> 4)) * 2);

    int u          = blockIdx.x * CHUNK;
    const int uend = min(u + CHUNK, UNITS);

    while (u < uend) {
        const int qt = u >> 5;
        const int k0 = u & 31;
        const int k1 = min(32, k0 + (uend - u));
        const int b  = qt >> 8;
        const int h  = (qt >> 4) & 15;
        const int qb = qt & 15;
        const int bh = b * NH + h;

        const __half* Qg = g_Q + ((size_t)bh * NS + (size_t)qb * 128) * DH;
        const __half* Kg = g_K + (size_t)bh * NS * DH;
        const __half* Vg = g_V + (size_t)bh * NS * DH;

        __syncthreads();   // previous segment fully done with smem

        #pragma unroll
        for (int it = 0; it < 8; it++) {
            int i = it * 128 + tid;
            int r = i >> 3, c8 = i & 7;
            *(uint4*)&sm[r * HSTR + c8 * 8] = *(const uint4*)&Qg[r * 64 + c8 * 8];
        }
        __syncthreads();

        uint32_t aq[2][4][4];
        #pragma unroll
        for (int mb = 0; mb < 2; mb++)
            #pragma unroll
            for (int kk = 0; kk < 4; kk++)
                LDSM_X4(aq[mb][kk][0], aq[mb][kk][1], aq[mb][kk][2], aq[mb][kk][3],
                        smb + a_lofs + (uint32_t)(mb * 16 * HSTR * 2 + kk * 32));
        __syncthreads();   // all aq reads done before cp.async overwrites

        {
            const uint32_t cur = (uint32_t)(k0 & 1);
            const __half* Ksrc = Kg + (size_t)k0 * 64 * DH;
            const __half* Vsrc = Vg + (size_t)k0 * 64 * DH;
            #pragma unroll
            for (int it = 0; it < 4; it++) {
                int i = it * 128 + tid;
                int r = i >> 3, c8 = i & 7;
                uint32_t off = (uint32_t)(r * HSTR + c8 * 8) * 2;
                CP_ASYNC16(smb + cur * KBUF_B + off,
                           (const char*)(Ksrc + r * 64 + c8 * 8));
                CP_ASYNC16(smb + 2 * KBUF_B + cur * KBUF_B + off,
                           (const char*)(Vsrc + r * 64 + c8 * 8));
            }
            CP_COMMIT();
        }

        float cO[2][8][4];
        float lf[2][2];
        #pragma unroll
        for (int mb = 0; mb < 2; mb++) {
            #pragma unroll
            for (int nb = 0; nb < 8; nb++)
                #pragma unroll
                for (int r = 0; r < 4; r++) cO[mb][nb][r] = 0.0f;
            lf[mb][0] = 0.0f;
            lf[mb][1] = 0.0f;
        }

        for (int kt = k0; kt < k1; kt++) {
            const uint32_t cur = (uint32_t)(kt & 1);
            CP_WAIT0();
            __syncthreads();

            if (kt + 1 < k1) {
                const __half* Ksrc = Kg + (size_t)(kt + 1) * 64 * DH;
                const __half* Vsrc = Vg + (size_t)(kt + 1) * 64 * DH;
                const uint32_t nxt = cur ^ 1u;
                #pragma unroll
                for (int it = 0; it < 4; it++) {
                    int i = it * 128 + tid;
                    int r = i >> 3, c8 = i & 7;
                    uint32_t off = (uint32_t)(r * HSTR + c8 * 8) * 2;
                    CP_ASYNC16(smb + nxt * KBUF_B + off,
                               (const char*)(Ksrc + r * 64 + c8 * 8));
                    CP_ASYNC16(smb + 2 * KBUF_B + nxt * KBUF_B + off,
                               (const char*)(Vsrc + r * 64 + c8 * 8));
                }
                CP_COMMIT();
            }

            const uint32_t kaddr = smb + cur * KBUF_B + k_lofs;
            const uint32_t vaddr = smb + 2 * KBUF_B + cur * KBUF_B + v_lofs;

            uint32_t ap[2][4][4];
            #pragma unroll
            for (int nb2 = 0; nb2 < 4; nb2++) {
                float cS[2][2][4];
                #pragma unroll
                for (int mb = 0; mb < 2; mb++)
                    #pragma unroll
                    for (int n = 0; n < 2; n++)
                        #pragma unroll
                        for (int r = 0; r < 4; r++) cS[mb][n][r] = 0.0f;

                #pragma unroll
                for (int kk = 0; kk < 4; kk++) {
                    uint32_t b0, b1, b2, b3;
                    LDSM_X4(b0, b1, b2, b3,
                            kaddr + (uint32_t)(nb2 * 16 * HSTR * 2 + kk * 32));
                    #pragma unroll
                    for (int mb = 0; mb < 2; mb++) {
                        mma_f16(cS[mb][0], aq[mb][kk], b0, b1);
                        mma_f16(cS[mb][1], aq[mb][kk], b2, b3);
                    }
                }
                #pragma unroll
                for (int mb = 0; mb < 2; mb++) {
                    ap[mb][nb2][0] = ex2_f16x2(pack_h2(cS[mb][0][0], cS[mb][0][1]));
                    ap[mb][nb2][1] = ex2_f16x2(pack_h2(cS[mb][0][2], cS[mb][0][3]));
                    ap[mb][nb2][2] = ex2_f16x2(pack_h2(cS[mb][1][0], cS[mb][1][1]));
                    ap[mb][nb2][3] = ex2_f16x2(pack_h2(cS[mb][1][2], cS[mb][1][3]));
                }
            }

            #pragma unroll
            for (int kk = 0; kk < 4; kk++) {
                #pragma unroll
                for (int nb2 = 0; nb2 < 4; nb2++) {
                    uint32_t b0, b1, b2, b3;
                    LDSM_X4_T(b0, b1, b2, b3,
                              vaddr + (uint32_t)(kk * 16 * HSTR * 2 + nb2 * 32));
                    #pragma unroll
                    for (int mb = 0; mb < 2; mb++) {
                        mma_f16(cO[mb][2 * nb2],     ap[mb][kk], b0, b1);
                        mma_f16(cO[mb][2 * nb2 + 1], ap[mb][kk], b2, b3);
                    }
                }
            }

            #pragma unroll
            for (int mb = 0; mb < 2; mb++) {
                __half2 sg = __hadd2(as_h2(ap[mb][0][0]), as_h2(ap[mb][0][2]));
                __half2 sh = __hadd2(as_h2(ap[mb][0][1]), as_h2(ap[mb][0][3]));
                #pragma unroll
                for (int kk = 1; kk < 4; kk++) {
                    sg = __hadd2(sg, __hadd2(as_h2(ap[mb][kk][0]), as_h2(ap[mb][kk][2])));
                    sh = __hadd2(sh, __hadd2(as_h2(ap[mb][kk][1]), as_h2(ap[mb][kk][3])));
                }
                float2 fg = __half22float2(sg);
                float2 fh = __half22float2(sh);
                lf[mb][0] += fg.x + fg.y;
                lf[mb][1] += fh.x + fh.y;
            }
        }

        // ---- segment epilogue ----
        #pragma unroll
        for (int mb = 0; mb < 2; mb++)
            #pragma unroll
            for (int rr = 0; rr < 2; rr++) {
                lf[mb][rr] += __shfl_xor_sync(0xffffffffu, lf[mb][rr], 1);
                lf[mb][rr] += __shfl_xor_sync(0xffffffffu, lf[mb][rr], 2);
            }

        if (k0 == 0 && k1 == 32) {
            // full coverage: normalize in registers, write final output
            float* outq = out + ((size_t)(b * NS) + (size_t)qb * 128) * ND + h * DH;
            #pragma unroll
            for (int mb = 0; mb < 2; mb++) {
                const float inv0 = 1.0f / lf[mb][0];
                const float inv1 = 1.0f / lf[mb][1];
                const int rl = r0 + mb * 16 + g;
                #pragma unroll
                for (int nb = 0; nb < 8; nb++) {
                    *(float2*)&outq[(size_t)rl * ND + nb * 8 + 2 * t] =
                        make_float2(cO[mb][nb][0] * inv0, cO[mb][nb][1] * inv0);
                    *(float2*)&outq[(size_t)(rl + 8) * ND + nb * 8 + 2 * t] =
                        make_float2(cO[mb][nb][2] * inv1, cO[mb][nb][3] * inv1);
                }
            }
        } else {
            // split tile: write unnormalized partial slice for combine pass
            const int slice = (k0 == 0) ? 0 : 1;
            float* Os = g_pO[slice][qt];
            float* Ls = g_pL[slice][qt];
            #pragma unroll
            for (int mb = 0; mb < 2; mb++) {
                const int rl = r0 + mb * 16 + g;
                #pragma unroll
                for (int nb = 0; nb < 8; nb++) {
                    *(float2*)&Os[rl * 64 + nb * 8 + 2 * t] =
                        make_float2(cO[mb][nb][0], cO[mb][nb][1]);
                    *(float2*)&Os[(rl + 8) * 64 + nb * 8 + 2 * t] =
                        make_float2(cO[mb][nb][2], cO[mb][nb][3]);
                }
                if (t == 0) {
                    Ls[rl]     = lf[mb][0];
                    Ls[rl + 8] = lf[mb][1];
                }
            }
        }

        u += k1 - k0;
    }
}

// ---------------------------------------------------------------------------
// Kernel 3: combine SPLIT tiles only (attn wrote full-coverage tiles
// directly). Split predicate is identical chunk arithmetic -> exactly
// complementary to attn's direct-write condition.
// ---------------------------------------------------------------------------
__global__ __launch_bounds__(256) void combine_kernel(float* __restrict__ out)
{
    const int idx  = blockIdx.x * 256 + threadIdx.x;   // one float4 each
    const int col4 = idx & 15;
    const int rowg = idx >> 4;
    const int qt   = rowg >> 7;
    const int row  = rowg & 127;

    // q-tile split iff a chunk boundary (multiple of CHUNK) lies strictly inside
    const int start = qt * 32;
    const int i0    = start / CHUNK + 1;
    const bool split = (i0 * CHUNK) < (start + 32);
    if (!split) return;   // attn already wrote this tile

    float l = g_pL[0][qt][row] + g_pL[1][qt][row];
    float4 s  = *(const float4*)&g_pO[0][qt][row * 64 + 4 * col4];
    float4 s1 = *(const float4*)&g_pO[1][qt][row * 64 + 4 * col4];
    const float inv = 1.0f / l;

    const int b  = qt >> 8;
    const int h  = (qt >> 4) & 15;
    const int qb = qt & 15;
    float* o = out + ((size_t)b * NS + (size_t)qb * 128 + row) * ND + h * 64 + 4 * col4;
    *(float4*)o = make_float4((s.x + s1.x) * inv, (s.y + s1.y) * inv,
                              (s.z + s1.z) * inv, (s.w + s1.w) * inv);
}

// ---------------------------------------------------------------------------
extern "C" void kernel_launch(void* const* d_in, const int* in_sizes, int n_in,
                              void* d_out, int out_size)
{
    const float* seqs = (const float*)d_in[0];
    const float* Wq   = (const float*)d_in[1];
    const float* bq   = (const float*)d_in[2];
    const float* Wk   = (const float*)d_in[3];
    const float* bk   = (const float*)d_in[4];
    const float* Wv   = (const float*)d_in[5];
    const float* bv   = (const float*)d_in[6];
    float* out = (float*)d_out;
    (void)in_sizes; (void)n_in; (void)out_size;

    proj_kernel<<<dim3(NB * NS / 128, NH), 128>>>(seqs, Wq, bq, Wk, bk, Wv, bv);

    cudaFuncSetAttribute(attn_mma, cudaFuncAttributeMaxDynamicSharedMemorySize,
                         (int)ATTN_SMEM);
    attn_mma<<<GRID_ATTN, 128, ATTN_SMEM>>>(out);

    combine_kernel<<<(NQT * 128 * 16) / 256, 256>>>(out);
}